// round 1
// baseline (speedup 1.0000x reference)
#include <cuda_runtime.h>
#include <cstdint>

#define Bv 32
#define Tv 128
#define Dv 128
#define Hv 8
#define HDv 16
#define Lv 4
#define Vv 50257
#define NT (Bv*Tv)          // 4096 tokens
#define EPSv 1e-5f

// ---------------- scratch (device globals; no allocation allowed) ----------
__device__ float g_x[NT*Dv];
__device__ float g_h[NT*Dv];
__device__ float g_q[NT*Dv];
__device__ float g_k[NT*Dv];
__device__ float g_v[NT*Dv];
__device__ float g_o[NT*Dv];
__device__ float g_mlp[NT*4*Dv];
__device__ float g_nll[NT];

// ---------------- embedding ------------------------------------------------
__global__ void embed_k(const int* __restrict__ idx,
                        const float* __restrict__ tok_emb,
                        const float* __restrict__ pos_emb) {
    int tok = blockIdx.x, d = threadIdx.x;
    int t = tok & (Tv - 1);
    g_x[tok*Dv + d] = tok_emb[(size_t)idx[tok]*Dv + d] + pos_emb[t*Dv + d];
}

// ---------------- layernorm (one block per token, 128 threads) -------------
__global__ void ln_k(const float* __restrict__ in, float* __restrict__ out,
                     const float* __restrict__ gg, const float* __restrict__ bb) {
    int tok = blockIdx.x, d = threadIdx.x;
    float v = in[tok*Dv + d];
    __shared__ float r1[4], r2[4];
    float s = v;
    #pragma unroll
    for (int o = 16; o; o >>= 1) s += __shfl_xor_sync(0xffffffffu, s, o);
    if ((d & 31) == 0) r1[d >> 5] = s;
    __syncthreads();
    float mean = (r1[0] + r1[1] + r1[2] + r1[3]) * (1.f/Dv);
    float c = v - mean;
    float cs = c * c;
    #pragma unroll
    for (int o = 16; o; o >>= 1) cs += __shfl_xor_sync(0xffffffffu, cs, o);
    if ((d & 31) == 0) r2[d >> 5] = cs;
    __syncthreads();
    float var = (r2[0] + r2[1] + r2[2] + r2[3]) * (1.f/Dv);
    out[tok*Dv + d] = c * rsqrtf(var + EPSv) * gg[d] + bb[d];
}

// ---------------- fused QKV projection -------------------------------------
// wq/wk/wv layer slice layout: [H, D, HD]; output col j = h*HD+e
__global__ void qkv_k(const float* __restrict__ h,
                      const float* __restrict__ wq, const float* __restrict__ wk,
                      const float* __restrict__ wv) {
    int tok = blockIdx.x, j = threadIdx.x;
    __shared__ float hs[Dv];
    hs[j] = h[tok*Dv + j];
    __syncthreads();
    int hh = j >> 4, e = j & 15;
    const float* wqp = wq + (size_t)hh*Dv*HDv + e;
    const float* wkp = wk + (size_t)hh*Dv*HDv + e;
    const float* wvp = wv + (size_t)hh*Dv*HDv + e;
    float aq = 0.f, ak = 0.f, av = 0.f;
    #pragma unroll 8
    for (int d = 0; d < Dv; d++) {
        float a = hs[d];
        aq = fmaf(a, wqp[d*HDv], aq);
        ak = fmaf(a, wkp[d*HDv], ak);
        av = fmaf(a, wvp[d*HDv], av);
    }
    g_q[tok*Dv + j] = aq;
    g_k[tok*Dv + j] = ak;
    g_v[tok*Dv + j] = av;
}

// ---------------- attention (one block per (b,h), one thread per query) ----
__global__ void attn_k() {
    int bh = blockIdx.x;
    int b = bh >> 3, hh = bh & 7;
    int t = threadIdx.x;
    __shared__ float ks[Tv][HDv];
    __shared__ float vs[Tv][HDv];
    int base = (b*Tv + t)*Dv + hh*HDv;
    float qr[HDv];
    #pragma unroll
    for (int e = 0; e < HDv; e++) {
        ks[t][e] = g_k[base + e];
        vs[t][e] = g_v[base + e];
        qr[e]    = g_q[base + e];
    }
    __syncthreads();
    const float scale = 0.088388347648318447f;   // 128^-0.5 (n_embd, not head_size)
    float m = -1e30f, sum = 0.f;
    float o[HDv];
    #pragma unroll
    for (int e = 0; e < HDv; e++) o[e] = 0.f;
    for (int s = 0; s <= t; s++) {
        float sc = 0.f;
        #pragma unroll
        for (int e = 0; e < HDv; e++) sc = fmaf(qr[e], ks[s][e], sc);
        sc *= scale;
        float nm = fmaxf(m, sc);
        float corr = __expf(m - nm);
        float p = __expf(sc - nm);
        sum = sum * corr + p;
        #pragma unroll
        for (int e = 0; e < HDv; e++) o[e] = fmaf(o[e], corr, p * vs[s][e]);
        m = nm;
    }
    float inv = 1.f / sum;
    #pragma unroll
    for (int e = 0; e < HDv; e++) g_o[base + e] = o[e] * inv;
}

// ---------------- x += in @ W[128x128] + b ---------------------------------
__global__ void addmm128_k(const float* __restrict__ in, const float* __restrict__ W,
                           const float* __restrict__ bias, float* __restrict__ x) {
    int tok = blockIdx.x, j = threadIdx.x;
    __shared__ float s[Dv];
    s[j] = in[tok*Dv + j];
    __syncthreads();
    float acc = bias[j];
    #pragma unroll 8
    for (int d = 0; d < Dv; d++) acc = fmaf(s[d], W[d*Dv + j], acc);
    x[tok*Dv + j] += acc;
}

// ---------------- mlp up: relu(h @ w1[128x512] + b1) -----------------------
__global__ void mlp1_k(const float* __restrict__ h, const float* __restrict__ w1,
                       const float* __restrict__ b1) {
    int tok = blockIdx.x, j = threadIdx.x;     // 512 threads
    __shared__ float s[Dv];
    if (j < Dv) s[j] = h[tok*Dv + j];
    __syncthreads();
    float acc = b1[j];
    #pragma unroll 8
    for (int d = 0; d < Dv; d++) acc = fmaf(s[d], w1[d*4*Dv + j], acc);
    g_mlp[tok*4*Dv + j] = fmaxf(acc, 0.f);
}

// ---------------- mlp down: x += mlp @ w2[512x128] + b2 --------------------
__global__ void mlp2_k(const float* __restrict__ w2, const float* __restrict__ b2) {
    int tok = blockIdx.x, j = threadIdx.x;     // 128 threads
    __shared__ float s[4*Dv];
    #pragma unroll
    for (int i = j; i < 4*Dv; i += Dv) s[i] = g_mlp[tok*4*Dv + i];
    __syncthreads();
    float acc = b2[j];
    #pragma unroll 8
    for (int d = 0; d < 4*Dv; d++) acc = fmaf(s[d], w2[d*Dv + j], acc);
    g_x[tok*Dv + j] += acc;
}

// ---------------- LM head: out[4096, 50257] = h @ lm_w + lm_b --------------
// block: 256 threads = 64 vocab-threads x 4 token-groups
// thread computes 4 vocab cols (stride 64) x 8 token rows
__global__ void __launch_bounds__(256) logits_k(
        const float* __restrict__ h, const float* __restrict__ lm_w,
        const float* __restrict__ lm_b, float* __restrict__ out) {
    __shared__ float a[32][Dv];
    int tx = threadIdx.x & 63;
    int ty = threadIdx.x >> 6;               // 0..3
    int tok0 = blockIdx.y * 32;
    // cooperative load of 32x128 activation tile
    for (int i = threadIdx.x; i < 32*Dv; i += 256)
        a[i >> 7][i & 127] = h[(tok0 + (i >> 7))*Dv + (i & 127)];
    __syncthreads();

    int n0 = blockIdx.x * 256 + tx;
    int nn[4]; bool ok[4];
    #pragma unroll
    for (int k = 0; k < 4; k++) {
        int n = n0 + 64*k;
        ok[k] = (n < Vv);
        nn[k] = ok[k] ? n : (Vv - 1);
    }
    float acc[4][8];
    #pragma unroll
    for (int k = 0; k < 4; k++) {
        float bias = lm_b[nn[k]];
        #pragma unroll
        for (int r = 0; r < 8; r++) acc[k][r] = bias;
    }
    int r0 = ty * 8;
    #pragma unroll 4
    for (int d = 0; d < Dv; d++) {
        float w0 = lm_w[(size_t)d*Vv + nn[0]];
        float w1 = lm_w[(size_t)d*Vv + nn[1]];
        float w2 = lm_w[(size_t)d*Vv + nn[2]];
        float w3 = lm_w[(size_t)d*Vv + nn[3]];
        #pragma unroll
        for (int r = 0; r < 8; r++) {
            float av = a[r0 + r][d];
            acc[0][r] = fmaf(av, w0, acc[0][r]);
            acc[1][r] = fmaf(av, w1, acc[1][r]);
            acc[2][r] = fmaf(av, w2, acc[2][r]);
            acc[3][r] = fmaf(av, w3, acc[3][r]);
        }
    }
    #pragma unroll
    for (int k = 0; k < 4; k++) {
        if (!ok[k]) continue;
        #pragma unroll
        for (int r = 0; r < 8; r++)
            out[(size_t)(tok0 + r0 + r)*Vv + nn[k]] = acc[k][r];
    }
}

// ---------------- per-token NLL --------------------------------------------
__global__ void loss_k(const float* __restrict__ logits, const int* __restrict__ targets) {
    int tok = blockIdx.x;
    const float* row = logits + (size_t)tok * Vv;
    int tid = threadIdx.x;                    // 256
    float m = -1e30f, s = 0.f;
    for (int i = tid; i < Vv; i += 256) {
        float v = row[i];
        if (v > m) { s = s * __expf(m - v) + 1.f; m = v; }
        else       { s += __expf(v - m); }
    }
    __shared__ float sm[256], ss[256];
    sm[tid] = m; ss[tid] = s;
    __syncthreads();
    for (int o = 128; o; o >>= 1) {
        if (tid < o) {
            float m2 = sm[tid + o], s2 = ss[tid + o];
            float nm = fmaxf(sm[tid], m2);
            ss[tid] = ss[tid] * __expf(sm[tid] - nm) + s2 * __expf(m2 - nm);
            sm[tid] = nm;
        }
        __syncthreads();
    }
    if (tid == 0) {
        float lse = sm[0] + logf(ss[0]);
        g_nll[tok] = lse - row[targets[tok]];
    }
}

__global__ void loss_reduce_k(float* __restrict__ out) {
    int tid = threadIdx.x;                    // 256
    float s = 0.f;
    for (int i = tid; i < NT; i += 256) s += g_nll[i];
    #pragma unroll
    for (int o = 16; o; o >>= 1) s += __shfl_xor_sync(0xffffffffu, s, o);
    __shared__ float r[8];
    if ((tid & 31) == 0) r[tid >> 5] = s;
    __syncthreads();
    if (tid == 0) {
        float t = 0.f;
        #pragma unroll
        for (int i = 0; i < 8; i++) t += r[i];
        out[(size_t)NT * Vv] = t * (1.f / NT);
    }
}

// ---------------- launcher -------------------------------------------------
extern "C" void kernel_launch(void* const* d_in, const int* in_sizes, int n_in,
                              void* d_out, int out_size) {
    const int*   idx     = (const int*)d_in[0];
    const int*   targets = (const int*)d_in[1];
    const float* tok_emb = (const float*)d_in[2];
    const float* pos_emb = (const float*)d_in[3];
    const float* wq      = (const float*)d_in[4];
    const float* wk      = (const float*)d_in[5];
    const float* wv      = (const float*)d_in[6];
    const float* wproj   = (const float*)d_in[7];
    const float* bproj   = (const float*)d_in[8];
    const float* w1      = (const float*)d_in[9];
    const float* b1      = (const float*)d_in[10];
    const float* w2      = (const float*)d_in[11];
    const float* b2      = (const float*)d_in[12];
    const float* ln1_g   = (const float*)d_in[13];
    const float* ln1_b   = (const float*)d_in[14];
    const float* ln2_g   = (const float*)d_in[15];
    const float* ln2_b   = (const float*)d_in[16];
    const float* lnf_g   = (const float*)d_in[17];
    const float* lnf_b   = (const float*)d_in[18];
    const float* lm_w    = (const float*)d_in[19];
    const float* lm_b    = (const float*)d_in[20];
    float* out = (float*)d_out;

    float *px, *ph;
    cudaGetSymbolAddress((void**)&px, g_x);
    cudaGetSymbolAddress((void**)&ph, g_h);

    embed_k<<<NT, Dv>>>(idx, tok_emb, pos_emb);

    for (int l = 0; l < Lv; l++) {
        const float* wq_l = wq + (size_t)l*Hv*Dv*HDv;
        const float* wk_l = wk + (size_t)l*Hv*Dv*HDv;
        const float* wv_l = wv + (size_t)l*Hv*Dv*HDv;
        ln_k<<<NT, Dv>>>(px, ph, ln1_g + l*Dv, ln1_b + l*Dv);
        qkv_k<<<NT, Dv>>>(ph, wq_l, wk_l, wv_l);
        attn_k<<<Bv*Hv, Tv>>>();
        {
            float* po;
            cudaGetSymbolAddress((void**)&po, g_o);
            addmm128_k<<<NT, Dv>>>(po, wproj + (size_t)l*Dv*Dv, bproj + l*Dv, px);
        }
        ln_k<<<NT, Dv>>>(px, ph, ln2_g + l*Dv, ln2_b + l*Dv);
        mlp1_k<<<NT, 4*Dv>>>(ph, w1 + (size_t)l*Dv*4*Dv, b1 + l*4*Dv);
        mlp2_k<<<NT, Dv>>>(w2 + (size_t)l*4*Dv*Dv, b2 + l*Dv);
    }

    ln_k<<<NT, Dv>>>(px, ph, lnf_g, lnf_b);

    dim3 lgrid((Vv + 255) / 256, NT / 32);
    logits_k<<<lgrid, 256>>>(ph, lm_w, lm_b, out);

    loss_k<<<NT, 256>>>(out, targets);
    loss_reduce_k<<<1, 256>>>(out);
}

// round 5
// speedup vs baseline: 1.4187x; 1.4187x over previous
#include <cuda_runtime.h>
#include <cstdint>

#define Bv 32
#define Tv 128
#define Dv 128
#define Hv 8
#define HDv 16
#define Lv 4
#define Vv 50257
#define NT (Bv*Tv)          // 4096 tokens
#define EPSv 1e-5f
#define NBLK 197            // ceil(V/256) vocab tiles in logits kernel

// ---------------- scratch (device globals; no allocation allowed) ----------
__device__ float g_x[NT*Dv];
__device__ float g_h[NT*Dv];
__device__ float g_q[NT*Dv];
__device__ float g_k[NT*Dv];
__device__ float g_v[NT*Dv];
__device__ float g_o[NT*Dv];
__device__ float g_mlp[NT*4*Dv];
__device__ float g_pm[NT*NBLK];
__device__ float g_ps[NT*NBLK];
__device__ float g_nll[NT];

// ---------------- embedding ------------------------------------------------
__global__ void embed_k(const int* __restrict__ idx,
                        const float* __restrict__ tok_emb,
                        const float* __restrict__ pos_emb) {
    int tok = blockIdx.x, d = threadIdx.x;
    int t = tok & (Tv - 1);
    g_x[tok*Dv + d] = tok_emb[(size_t)idx[tok]*Dv + d] + pos_emb[t*Dv + d];
}

// ---------------- layernorm (one block per token, 128 threads) -------------
__global__ void ln_k(const float* __restrict__ in, float* __restrict__ out,
                     const float* __restrict__ gg, const float* __restrict__ bb) {
    int tok = blockIdx.x, d = threadIdx.x;
    float v = in[tok*Dv + d];
    __shared__ float r1[4], r2[4];
    float s = v;
    #pragma unroll
    for (int o = 16; o; o >>= 1) s += __shfl_xor_sync(0xffffffffu, s, o);
    if ((d & 31) == 0) r1[d >> 5] = s;
    __syncthreads();
    float mean = (r1[0] + r1[1] + r1[2] + r1[3]) * (1.f/Dv);
    float c = v - mean;
    float cs = c * c;
    #pragma unroll
    for (int o = 16; o; o >>= 1) cs += __shfl_xor_sync(0xffffffffu, cs, o);
    if ((d & 31) == 0) r2[d >> 5] = cs;
    __syncthreads();
    float var = (r2[0] + r2[1] + r2[2] + r2[3]) * (1.f/Dv);
    out[tok*Dv + d] = c * rsqrtf(var + EPSv) * gg[d] + bb[d];
}

// ---------------- token-tiled body GEMM ------------------------------------
// block = 256 thr: tx = tid&31 (4 cols, stride 32), ty = tid>>5 (8 groups x 4 rows)
// tile: 32 tokens x 128 cols.  A:[NT,K] row-major, W:[K,N] row-major.
template<int RELU, int ADDRES>
__global__ void __launch_bounds__(256) gemm_body_k(
        const float* __restrict__ A, const float* __restrict__ W,
        const float* __restrict__ bias, float* __restrict__ out,
        int N, int K) {
    __shared__ float as[32][128];
    int tid = threadIdx.x;
    int tx = tid & 31, ty = tid >> 5;
    int tok0 = blockIdx.y * 32;
    int n0 = blockIdx.x * 128 + tx;
    float acc[4][4];
    #pragma unroll
    for (int k = 0; k < 4; k++) {
        float b = bias[n0 + 32*k];
        #pragma unroll
        for (int r = 0; r < 4; r++) acc[k][r] = b;
    }
    for (int kc = 0; kc < K; kc += 128) {
        for (int i = tid; i < 32*128; i += 256)
            as[i >> 7][i & 127] = A[(size_t)(tok0 + (i >> 7))*K + kc + (i & 127)];
        __syncthreads();
        #pragma unroll 4
        for (int d = 0; d < 128; d++) {
            const float* wr = W + (size_t)(kc + d)*N + n0;
            float w0 = wr[0], w1 = wr[32], w2 = wr[64], w3 = wr[96];
            #pragma unroll
            for (int r = 0; r < 4; r++) {
                float av = as[ty*4 + r][d];          // broadcast LDS
                acc[0][r] = fmaf(av, w0, acc[0][r]);
                acc[1][r] = fmaf(av, w1, acc[1][r]);
                acc[2][r] = fmaf(av, w2, acc[2][r]);
                acc[3][r] = fmaf(av, w3, acc[3][r]);
            }
        }
        __syncthreads();
    }
    #pragma unroll
    for (int k = 0; k < 4; k++)
        #pragma unroll
        for (int r = 0; r < 4; r++) {
            float v = acc[k][r];
            if (RELU) v = fmaxf(v, 0.f);
            size_t o = (size_t)(tok0 + ty*4 + r)*N + n0 + 32*k;
            if (ADDRES) out[o] += v; else out[o] = v;
        }
}

// ---------------- fused QKV projection (token-tiled) -----------------------
// weights per layer: [H,D,HD]; output col j -> w[(j>>4)*D*HD + d*HD + (j&15)]
__global__ void __launch_bounds__(256) qkv_k2(const float* __restrict__ h,
        const float* __restrict__ wq, const float* __restrict__ wk,
        const float* __restrict__ wv) {
    __shared__ float as[32][128];
    int tid = threadIdx.x;
    int tx = tid & 31, ty = tid >> 5;
    int tok0 = blockIdx.x * 32;
    for (int i = tid; i < 32*128; i += 256)
        as[i >> 7][i & 127] = h[(size_t)(tok0 + (i >> 7))*Dv + (i & 127)];
    __syncthreads();
    int off[4];
    #pragma unroll
    for (int k = 0; k < 4; k++)
        off[k] = ((tx >> 4) + 2*k)*Dv*HDv + (tx & 15);
    float aq[4][4], ak[4][4], av_[4][4];
    #pragma unroll
    for (int k = 0; k < 4; k++)
        #pragma unroll
        for (int r = 0; r < 4; r++) { aq[k][r]=0.f; ak[k][r]=0.f; av_[k][r]=0.f; }
    #pragma unroll 2
    for (int d = 0; d < Dv; d++) {
        float wqv[4], wkv[4], wvv[4];
        #pragma unroll
        for (int k = 0; k < 4; k++) {
            wqv[k] = wq[off[k] + d*HDv];
            wkv[k] = wk[off[k] + d*HDv];
            wvv[k] = wv[off[k] + d*HDv];
        }
        #pragma unroll
        for (int r = 0; r < 4; r++) {
            float a = as[ty*4 + r][d];
            #pragma unroll
            for (int k = 0; k < 4; k++) {
                aq[k][r]  = fmaf(a, wqv[k], aq[k][r]);
                ak[k][r]  = fmaf(a, wkv[k], ak[k][r]);
                av_[k][r] = fmaf(a, wvv[k], av_[k][r]);
            }
        }
    }
    #pragma unroll
    for (int k = 0; k < 4; k++)
        #pragma unroll
        for (int r = 0; r < 4; r++) {
            size_t o = (size_t)(tok0 + ty*4 + r)*Dv + tx + 32*k;
            g_q[o] = aq[k][r];
            g_k[o] = ak[k][r];
            g_v[o] = av_[k][r];
        }
}

// ---------------- attention (one block per (b,h), one thread per query) ----
__global__ void attn_k() {
    int bh = blockIdx.x;
    int b = bh >> 3, hh = bh & 7;
    int t = threadIdx.x;
    __shared__ float ks[Tv][HDv];
    __shared__ float vs[Tv][HDv];
    int base = (b*Tv + t)*Dv + hh*HDv;
    float qr[HDv];
    #pragma unroll
    for (int e = 0; e < HDv; e++) {
        ks[t][e] = g_k[base + e];
        vs[t][e] = g_v[base + e];
        qr[e]    = g_q[base + e];
    }
    __syncthreads();
    const float scale = 0.088388347648318447f;   // 128^-0.5 (n_embd, not head_size)
    float m = -1e30f, sum = 0.f;
    float o[HDv];
    #pragma unroll
    for (int e = 0; e < HDv; e++) o[e] = 0.f;
    for (int s = 0; s <= t; s++) {
        float sc = 0.f;
        #pragma unroll
        for (int e = 0; e < HDv; e++) sc = fmaf(qr[e], ks[s][e], sc);
        sc *= scale;
        float nm = fmaxf(m, sc);
        float corr = __expf(m - nm);
        float p = __expf(sc - nm);
        sum = sum * corr + p;
        #pragma unroll
        for (int e = 0; e < HDv; e++) o[e] = fmaf(o[e], corr, p * vs[s][e]);
        m = nm;
    }
    float inv = 1.f / sum;
    #pragma unroll
    for (int e = 0; e < HDv; e++) g_o[base + e] = o[e] * inv;
}

// ---------------- LM head + fused softmax partials -------------------------
// block: 256 thr = 64 tx x 4 ty; 32 tokens x 256 vocab cols per block;
// thread: 4 cols (stride 64) x 8 rows.
__global__ void __launch_bounds__(256) logits_k(
        const float* __restrict__ h, const float* __restrict__ lm_w,
        const float* __restrict__ lm_b, float* __restrict__ out) {
    __shared__ float a[32][Dv];
    __shared__ float red_m[32][2], red_s[32][2];
    int tx = threadIdx.x & 63;
    int ty = threadIdx.x >> 6;               // 0..3
    int tok0 = blockIdx.y * 32;
    for (int i = threadIdx.x; i < 32*Dv; i += 256)
        a[i >> 7][i & 127] = h[(size_t)(tok0 + (i >> 7))*Dv + (i & 127)];
    __syncthreads();

    int n0 = blockIdx.x * 256 + tx;
    int nn[4]; bool ok[4];
    #pragma unroll
    for (int k = 0; k < 4; k++) {
        int n = n0 + 64*k;
        ok[k] = (n < Vv);
        nn[k] = ok[k] ? n : (Vv - 1);
    }
    float acc[4][8];
    #pragma unroll
    for (int k = 0; k < 4; k++) {
        float bias = lm_b[nn[k]];
        #pragma unroll
        for (int r = 0; r < 8; r++) acc[k][r] = bias;
    }
    int r0 = ty * 8;
    #pragma unroll 4
    for (int d = 0; d < Dv; d++) {
        float w0 = lm_w[(size_t)d*Vv + nn[0]];
        float w1 = lm_w[(size_t)d*Vv + nn[1]];
        float w2 = lm_w[(size_t)d*Vv + nn[2]];
        float w3 = lm_w[(size_t)d*Vv + nn[3]];
        #pragma unroll
        for (int r = 0; r < 8; r++) {
            float av = a[r0 + r][d];
            acc[0][r] = fmaf(av, w0, acc[0][r]);
            acc[1][r] = fmaf(av, w1, acc[1][r]);
            acc[2][r] = fmaf(av, w2, acc[2][r]);
            acc[3][r] = fmaf(av, w3, acc[3][r]);
        }
    }
    // store logits
    #pragma unroll
    for (int k = 0; k < 4; k++) {
        if (!ok[k]) continue;
        #pragma unroll
        for (int r = 0; r < 8; r++)
            out[(size_t)(tok0 + r0 + r)*Vv + nn[k]] = acc[k][r];
    }
    // per-token (max, sumexp) partials for this 256-col tile.
    // warp-max-first: no exps in the merge path.
    int lane = tx & 31, wsel = tx >> 5;
    #pragma unroll
    for (int r = 0; r < 8; r++) {
        float m4 = -1e30f;
        #pragma unroll
        for (int k = 0; k < 4; k++) if (ok[k]) m4 = fmaxf(m4, acc[k][r]);
        #pragma unroll
        for (int o = 16; o; o >>= 1)
            m4 = fmaxf(m4, __shfl_xor_sync(0xffffffffu, m4, o));
        float s = 0.f;
        #pragma unroll
        for (int k = 0; k < 4; k++) if (ok[k]) s += __expf(acc[k][r] - m4);
        #pragma unroll
        for (int o = 16; o; o >>= 1) s += __shfl_xor_sync(0xffffffffu, s, o);
        if (lane == 0) { red_m[r0 + r][wsel] = m4; red_s[r0 + r][wsel] = s; }
    }
    __syncthreads();
    if (threadIdx.x < 32) {
        int i = threadIdx.x;
        float m1 = red_m[i][0], m2 = red_m[i][1];
        float M = fmaxf(m1, m2);
        float s = red_s[i][0]*__expf(m1 - M) + red_s[i][1]*__expf(m2 - M);
        g_pm[(size_t)(tok0 + i)*NBLK + blockIdx.x] = M;
        g_ps[(size_t)(tok0 + i)*NBLK + blockIdx.x] = s;
    }
}

// ---------------- per-token NLL from partials ------------------------------
__global__ void loss_token_k(const float* __restrict__ logits,
                             const int* __restrict__ targets) {
    int tok = blockIdx.x;
    int lane = threadIdx.x;                  // 32
    float m = -1e30f, s = 0.f;
    for (int i = lane; i < NBLK; i += 32) {
        float m2 = g_pm[(size_t)tok*NBLK + i];
        float s2 = g_ps[(size_t)tok*NBLK + i];
        float nm = fmaxf(m, m2);
        s = s*__expf(m - nm) + s2*__expf(m2 - nm);
        m = nm;
    }
    #pragma unroll
    for (int o = 16; o; o >>= 1) {
        float m2 = __shfl_xor_sync(0xffffffffu, m, o);
        float s2 = __shfl_xor_sync(0xffffffffu, s, o);
        float nm = fmaxf(m, m2);
        s = s*__expf(m - nm) + s2*__expf(m2 - nm);
        m = nm;
    }
    if (lane == 0) {
        float lse = m + logf(s);
        g_nll[tok] = lse - logits[(size_t)tok*Vv + targets[tok]];
    }
}

__global__ void loss_reduce_k(float* __restrict__ out) {
    int tid = threadIdx.x;                    // 256
    float s = 0.f;
    for (int i = tid; i < NT; i += 256) s += g_nll[i];
    #pragma unroll
    for (int o = 16; o; o >>= 1) s += __shfl_xor_sync(0xffffffffu, s, o);
    __shared__ float r[8];
    if ((tid & 31) == 0) r[tid >> 5] = s;
    __syncthreads();
    if (tid == 0) {
        float t = 0.f;
        #pragma unroll
        for (int i = 0; i < 8; i++) t += r[i];
        out[(size_t)NT * Vv] = t * (1.f / NT);
    }
}

// ---------------- launcher -------------------------------------------------
extern "C" void kernel_launch(void* const* d_in, const int* in_sizes, int n_in,
                              void* d_out, int out_size) {
    const int*   idx     = (const int*)d_in[0];
    const int*   targets = (const int*)d_in[1];
    const float* tok_emb = (const float*)d_in[2];
    const float* pos_emb = (const float*)d_in[3];
    const float* wq      = (const float*)d_in[4];
    const float* wk      = (const float*)d_in[5];
    const float* wv      = (const float*)d_in[6];
    const float* wproj   = (const float*)d_in[7];
    const float* bproj   = (const float*)d_in[8];
    const float* w1      = (const float*)d_in[9];
    const float* b1      = (const float*)d_in[10];
    const float* w2      = (const float*)d_in[11];
    const float* b2      = (const float*)d_in[12];
    const float* ln1_g   = (const float*)d_in[13];
    const float* ln1_b   = (const float*)d_in[14];
    const float* ln2_g   = (const float*)d_in[15];
    const float* ln2_b   = (const float*)d_in[16];
    const float* lnf_g   = (const float*)d_in[17];
    const float* lnf_b   = (const float*)d_in[18];
    const float* lm_w    = (const float*)d_in[19];
    const float* lm_b    = (const float*)d_in[20];
    float* out = (float*)d_out;

    float *px, *ph, *po, *pmlp;
    cudaGetSymbolAddress((void**)&px, g_x);
    cudaGetSymbolAddress((void**)&ph, g_h);
    cudaGetSymbolAddress((void**)&po, g_o);
    cudaGetSymbolAddress((void**)&pmlp, g_mlp);

    embed_k<<<NT, Dv>>>(idx, tok_emb, pos_emb);

    for (int l = 0; l < Lv; l++) {
        const float* wq_l = wq + (size_t)l*Hv*Dv*HDv;
        const float* wk_l = wk + (size_t)l*Hv*Dv*HDv;
        const float* wv_l = wv + (size_t)l*Hv*Dv*HDv;
        ln_k<<<NT, Dv>>>(px, ph, ln1_g + l*Dv, ln1_b + l*Dv);
        qkv_k2<<<NT/32, 256>>>(ph, wq_l, wk_l, wv_l);
        attn_k<<<Bv*Hv, Tv>>>();
        gemm_body_k<0,1><<<dim3(1, NT/32), 256>>>(
            po, wproj + (size_t)l*Dv*Dv, bproj + l*Dv, px, Dv, Dv);
        ln_k<<<NT, Dv>>>(px, ph, ln2_g + l*Dv, ln2_b + l*Dv);
        gemm_body_k<1,0><<<dim3(4, NT/32), 256>>>(
            ph, w1 + (size_t)l*Dv*4*Dv, b1 + l*4*Dv, pmlp, 4*Dv, Dv);
        gemm_body_k<0,1><<<dim3(1, NT/32), 256>>>(
            pmlp, w2 + (size_t)l*4*Dv*Dv, b2 + l*Dv, px, Dv, 4*Dv);
    }

    ln_k<<<NT, Dv>>>(px, ph, lnf_g, lnf_b);

    dim3 lgrid(NBLK, NT / 32);
    logits_k<<<lgrid, 256>>>(ph, lm_w, lm_b, out);

    loss_token_k<<<NT, 32>>>(out, targets);
    loss_reduce_k<<<1, 256>>>(out);
}

// round 10
// speedup vs baseline: 2.0908x; 1.4737x over previous
#include <cuda_runtime.h>
#include <cuda_bf16.h>
#include <cstdint>

#define Bv 32
#define Tv 128
#define Dv 128
#define Hv 8
#define HDv 16
#define Lv 4
#define Vv 50257
#define NT (Bv*Tv)          // 4096 tokens
#define EPSv 1e-5f
#define Wpad 50304          // 393*128 padded vocab
#define NTI 393             // vocab tiles of 128 in logits kernel

// ---------------- scratch (device globals; no allocation allowed) ----------
__device__ float g_x[NT*Dv];
__device__ float g_h[NT*Dv];
__device__ float g_q[NT*Dv];
__device__ float g_k[NT*Dv];
__device__ float g_v[NT*Dv];
__device__ float g_o[NT*Dv];
__device__ float g_mlp[NT*4*Dv];
__device__ float g_pm[NT*NTI];
__device__ float g_ps[NT*NTI];
__device__ float g_nll[NT];
__device__ __align__(16) __nv_bfloat16 g_hh[NT*Dv];
__device__ __align__(16) __nv_bfloat16 g_hl[NT*Dv];
__device__ __align__(16) __nv_bfloat16 g_wh[Dv*Wpad];
__device__ __align__(16) __nv_bfloat16 g_wl[Dv*Wpad];

// ---------------- warp-mma helpers (baseline PTX: sm_80+, no 'a' feats) ----
__device__ __forceinline__ uint32_t smem_u32(const void* p) {
    uint32_t a;
    asm("{ .reg .u64 t; cvta.to.shared.u64 t, %1; cvt.u32.u64 %0, t; }" : "=r"(a) : "l"(p));
    return a;
}
__device__ __forceinline__ void ldmA(uint32_t* a, uint32_t addr) {
    asm volatile("ldmatrix.sync.aligned.m8n8.x4.shared.b16 {%0,%1,%2,%3}, [%4];"
        : "=r"(a[0]), "=r"(a[1]), "=r"(a[2]), "=r"(a[3]) : "r"(addr));
}
__device__ __forceinline__ void ldmB(uint32_t* b, uint32_t addr) {
    asm volatile("ldmatrix.sync.aligned.m8n8.x2.trans.shared.b16 {%0,%1}, [%2];"
        : "=r"(b[0]), "=r"(b[1]) : "r"(addr));
}
__device__ __forceinline__ void mma16816(float* c, const uint32_t* a, const uint32_t* b) {
    asm volatile("mma.sync.aligned.m16n8k16.row.col.f32.bf16.bf16.f32 "
        "{%0,%1,%2,%3}, {%4,%5,%6,%7}, {%8,%9}, {%0,%1,%2,%3};"
        : "+f"(c[0]), "+f"(c[1]), "+f"(c[2]), "+f"(c[3])
        : "r"(a[0]), "r"(a[1]), "r"(a[2]), "r"(a[3]), "r"(b[0]), "r"(b[1]));
}

// ---------------- embedding ------------------------------------------------
__global__ void embed_k(const int* __restrict__ idx,
                        const float* __restrict__ tok_emb,
                        const float* __restrict__ pos_emb) {
    int tok = blockIdx.x, d = threadIdx.x;
    int t = tok & (Tv - 1);
    g_x[tok*Dv + d] = tok_emb[(size_t)idx[tok]*Dv + d] + pos_emb[t*Dv + d];
}

// ---------------- layernorm ------------------------------------------------
__global__ void ln_k(const float* __restrict__ in, float* __restrict__ out,
                     const float* __restrict__ gg, const float* __restrict__ bb) {
    int tok = blockIdx.x, d = threadIdx.x;
    float v = in[tok*Dv + d];
    __shared__ float r1[4], r2[4];
    float s = v;
    #pragma unroll
    for (int o = 16; o; o >>= 1) s += __shfl_xor_sync(0xffffffffu, s, o);
    if ((d & 31) == 0) r1[d >> 5] = s;
    __syncthreads();
    float mean = (r1[0] + r1[1] + r1[2] + r1[3]) * (1.f/Dv);
    float c = v - mean;
    float cs = c * c;
    #pragma unroll
    for (int o = 16; o; o >>= 1) cs += __shfl_xor_sync(0xffffffffu, cs, o);
    if ((d & 31) == 0) r2[d >> 5] = cs;
    __syncthreads();
    float var = (r2[0] + r2[1] + r2[2] + r2[3]) * (1.f/Dv);
    out[tok*Dv + d] = c * rsqrtf(var + EPSv) * gg[d] + bb[d];
}

// ---------------- token-tiled body GEMM ------------------------------------
template<int RELU, int ADDRES>
__global__ void __launch_bounds__(256) gemm_body_k(
        const float* __restrict__ A, const float* __restrict__ W,
        const float* __restrict__ bias, float* __restrict__ out,
        int N, int K) {
    __shared__ float as[32][128];
    int tid = threadIdx.x;
    int tx = tid & 31, ty = tid >> 5;
    int tok0 = blockIdx.y * 32;
    int n0 = blockIdx.x * 128 + tx;
    float acc[4][4];
    #pragma unroll
    for (int k = 0; k < 4; k++) {
        float b = bias[n0 + 32*k];
        #pragma unroll
        for (int r = 0; r < 4; r++) acc[k][r] = b;
    }
    for (int kc = 0; kc < K; kc += 128) {
        for (int i = tid; i < 32*128; i += 256)
            as[i >> 7][i & 127] = A[(size_t)(tok0 + (i >> 7))*K + kc + (i & 127)];
        __syncthreads();
        #pragma unroll 4
        for (int d = 0; d < 128; d++) {
            const float* wr = W + (size_t)(kc + d)*N + n0;
            float w0 = wr[0], w1 = wr[32], w2 = wr[64], w3 = wr[96];
            #pragma unroll
            for (int r = 0; r < 4; r++) {
                float av = as[ty*4 + r][d];
                acc[0][r] = fmaf(av, w0, acc[0][r]);
                acc[1][r] = fmaf(av, w1, acc[1][r]);
                acc[2][r] = fmaf(av, w2, acc[2][r]);
                acc[3][r] = fmaf(av, w3, acc[3][r]);
            }
        }
        __syncthreads();
    }
    #pragma unroll
    for (int k = 0; k < 4; k++)
        #pragma unroll
        for (int r = 0; r < 4; r++) {
            float v = acc[k][r];
            if (RELU) v = fmaxf(v, 0.f);
            size_t o = (size_t)(tok0 + ty*4 + r)*N + n0 + 32*k;
            if (ADDRES) out[o] += v; else out[o] = v;
        }
}

// ---------------- fused QKV projection -------------------------------------
__global__ void __launch_bounds__(256) qkv_k2(const float* __restrict__ h,
        const float* __restrict__ wq, const float* __restrict__ wk,
        const float* __restrict__ wv) {
    __shared__ float as[32][128];
    int tid = threadIdx.x;
    int tx = tid & 31, ty = tid >> 5;
    int tok0 = blockIdx.x * 32;
    for (int i = tid; i < 32*128; i += 256)
        as[i >> 7][i & 127] = h[(size_t)(tok0 + (i >> 7))*Dv + (i & 127)];
    __syncthreads();
    int off[4];
    #pragma unroll
    for (int k = 0; k < 4; k++)
        off[k] = ((tx >> 4) + 2*k)*Dv*HDv + (tx & 15);
    float aq[4][4], ak[4][4], av_[4][4];
    #pragma unroll
    for (int k = 0; k < 4; k++)
        #pragma unroll
        for (int r = 0; r < 4; r++) { aq[k][r]=0.f; ak[k][r]=0.f; av_[k][r]=0.f; }
    #pragma unroll 2
    for (int d = 0; d < Dv; d++) {
        float wqv[4], wkv[4], wvv[4];
        #pragma unroll
        for (int k = 0; k < 4; k++) {
            wqv[k] = wq[off[k] + d*HDv];
            wkv[k] = wk[off[k] + d*HDv];
            wvv[k] = wv[off[k] + d*HDv];
        }
        #pragma unroll
        for (int r = 0; r < 4; r++) {
            float a = as[ty*4 + r][d];
            #pragma unroll
            for (int k = 0; k < 4; k++) {
                aq[k][r]  = fmaf(a, wqv[k], aq[k][r]);
                ak[k][r]  = fmaf(a, wkv[k], ak[k][r]);
                av_[k][r] = fmaf(a, wvv[k], av_[k][r]);
            }
        }
    }
    #pragma unroll
    for (int k = 0; k < 4; k++)
        #pragma unroll
        for (int r = 0; r < 4; r++) {
            size_t o = (size_t)(tok0 + ty*4 + r)*Dv + tx + 32*k;
            g_q[o] = aq[k][r];
            g_k[o] = ak[k][r];
            g_v[o] = av_[k][r];
        }
}

// ---------------- attention ------------------------------------------------
__global__ void attn_k() {
    int bh = blockIdx.x;
    int b = bh >> 3, hh = bh & 7;
    int t = threadIdx.x;
    __shared__ float ks[Tv][HDv];
    __shared__ float vs[Tv][HDv];
    int base = (b*Tv + t)*Dv + hh*HDv;
    float qr[HDv];
    #pragma unroll
    for (int e = 0; e < HDv; e++) {
        ks[t][e] = g_k[base + e];
        vs[t][e] = g_v[base + e];
        qr[e]    = g_q[base + e];
    }
    __syncthreads();
    const float scale = 0.088388347648318447f;
    float m = -1e30f, sum = 0.f;
    float o[HDv];
    #pragma unroll
    for (int e = 0; e < HDv; e++) o[e] = 0.f;
    for (int s = 0; s <= t; s++) {
        float sc = 0.f;
        #pragma unroll
        for (int e = 0; e < HDv; e++) sc = fmaf(qr[e], ks[s][e], sc);
        sc *= scale;
        float nm = fmaxf(m, sc);
        float corr = __expf(m - nm);
        float p = __expf(sc - nm);
        sum = sum * corr + p;
        #pragma unroll
        for (int e = 0; e < HDv; e++) o[e] = fmaf(o[e], corr, p * vs[s][e]);
        m = nm;
    }
    float inv = 1.f / sum;
    #pragma unroll
    for (int e = 0; e < HDv; e++) g_o[base + e] = o[e] * inv;
}

// ---------------- split kernels (fp32 -> bf16 hi+lo) -----------------------
__global__ void hsplit_k(const float* __restrict__ h) {
    int i = blockIdx.x * 256 + threadIdx.x;
    float v = h[i];
    __nv_bfloat16 hi = __float2bfloat16_rn(v);
    g_hh[i] = hi;
    g_hl[i] = __float2bfloat16_rn(v - __bfloat162float(hi));
}
__global__ void wsplit_k(const float* __restrict__ lm_w) {
    int n = blockIdx.x * 128 + threadIdx.x;   // 0..50303
    int k = blockIdx.y;                       // 0..127
    float v = (n < Vv) ? lm_w[(size_t)k*Vv + n] : 0.f;
    __nv_bfloat16 hi = __float2bfloat16_rn(v);
    g_wh[(size_t)k*Wpad + n] = hi;
    g_wl[(size_t)k*Wpad + n] = __float2bfloat16_rn(v - __bfloat162float(hi));
}

// ---------------- LM head via mma.sync bf16 split, fused softmax -----------
// CTA: 64 tokens x 128 vocab cols, K=128. 256 thr = 8 warps (2m x 4n),
// warp tile 32x32 (2 mfrag x 4 nfrag of m16n8k16).
#define LDA 136
#define LDW 136
#define A_HALF (64*LDA)      // elements between hi and lo A planes
#define W_HALF (128*LDW)
#define SMEM_LM ((2*64*LDA + 2*128*LDW)*2 + 128*4 + 2*64*4*4)

__global__ void __launch_bounds__(256) logits_mma_k(float* __restrict__ out,
        const float* __restrict__ lm_b) {
    extern __shared__ char smem[];
    __nv_bfloat16* As = (__nv_bfloat16*)smem;                 // [2][64][LDA]
    __nv_bfloat16* Ws = As + 2*64*LDA;                        // [2][128][LDW]
    float* sbias = (float*)(Ws + 2*128*LDW);                  // [128]
    float* red_m = sbias + 128;                               // [64][4]
    float* red_s = red_m + 256;                               // [64][4]

    int tid = threadIdx.x;
    int tok0 = blockIdx.y * 64;
    int n0 = blockIdx.x * 128;

    // ---- load A (hi/lo) and W (hi/lo) tiles ----
    for (int i = tid; i < 64*16; i += 256) {
        int m = i >> 4, j = i & 15;
        size_t src = (size_t)(tok0 + m)*Dv + j*8;
        *(uint4*)(As + m*LDA + j*8)          = *(const uint4*)(g_hh + src);
        *(uint4*)(As + A_HALF + m*LDA + j*8) = *(const uint4*)(g_hl + src);
    }
    for (int i = tid; i < 128*16; i += 256) {
        int k = i >> 4, j = i & 15;
        size_t src = (size_t)k*Wpad + n0 + j*8;
        *(uint4*)(Ws + k*LDW + j*8)          = *(const uint4*)(g_wh + src);
        *(uint4*)(Ws + W_HALF + k*LDW + j*8) = *(const uint4*)(g_wl + src);
    }
    if (tid < 128) sbias[tid] = (n0 + tid < Vv) ? lm_b[n0 + tid] : 0.f;
    __syncthreads();

    int wid = tid >> 5, lane = tid & 31;
    int wm = wid >> 2, wn = wid & 3;
    int mbase = wm*32, nbase = wn*32;

    float acc[2][4][4];
    #pragma unroll
    for (int f = 0; f < 2; f++)
        #pragma unroll
        for (int g = 0; g < 4; g++)
            #pragma unroll
            for (int r = 0; r < 4; r++) acc[f][g][r] = 0.f;

    #pragma unroll
    for (int ks = 0; ks < 8; ks++) {
        int k0 = ks*16;
        uint32_t ah[2][4], al[2][4];
        #pragma unroll
        for (int f = 0; f < 2; f++) {
            const __nv_bfloat16* p =
                As + (mbase + f*16 + (lane & 15))*LDA + k0 + ((lane >> 4) << 3);
            ldmA(ah[f], smem_u32(p));
            ldmA(al[f], smem_u32(p + A_HALF));
        }
        uint32_t bh[4][2], bl[4][2];
        #pragma unroll
        for (int g = 0; g < 4; g++) {
            const __nv_bfloat16* p =
                Ws + (k0 + (lane & 15))*LDW + nbase + g*8;
            ldmB(bh[g], smem_u32(p));
            ldmB(bl[g], smem_u32(p + W_HALF));
        }
        #pragma unroll
        for (int f = 0; f < 2; f++)
            #pragma unroll
            for (int g = 0; g < 4; g++) {
                mma16816(acc[f][g], ah[f], bh[g]);
                mma16816(acc[f][g], ah[f], bl[g]);
                mma16816(acc[f][g], al[f], bh[g]);
            }
    }

    // ---- epilogue: bias, store (scalar: Vv odd => rows not 8B-aligned),
    //      per-row softmax partials ----
    int r_in = lane >> 2, cbase = (lane & 3)*2;
    #pragma unroll
    for (int f = 0; f < 2; f++) {
        #pragma unroll
        for (int half = 0; half < 2; half++) {
            int row = mbase + f*16 + r_in + 8*half;
            int tok = tok0 + row;
            float x[8];
            float lm = -1e30f;
            #pragma unroll
            for (int g = 0; g < 4; g++) {
                int cl = nbase + g*8 + cbase;
                float v0 = acc[f][g][2*half]     + sbias[cl];
                float v1 = acc[f][g][2*half + 1] + sbias[cl + 1];
                int n = n0 + cl;
                if (n < Vv)     out[(size_t)tok*Vv + n]     = v0;
                if (n + 1 < Vv) out[(size_t)tok*Vv + n + 1] = v1;
                if (n >= Vv)     v0 = -1e30f;
                if (n + 1 >= Vv) v1 = -1e30f;
                x[2*g] = v0; x[2*g+1] = v1;
                lm = fmaxf(lm, fmaxf(v0, v1));
            }
            lm = fmaxf(lm, __shfl_xor_sync(0xffffffffu, lm, 1));
            lm = fmaxf(lm, __shfl_xor_sync(0xffffffffu, lm, 2));
            float s = 0.f;
            #pragma unroll
            for (int j = 0; j < 8; j++) s += __expf(x[j] - lm);
            s += __shfl_xor_sync(0xffffffffu, s, 1);
            s += __shfl_xor_sync(0xffffffffu, s, 2);
            if ((lane & 3) == 0) { red_m[row*4 + wn] = lm; red_s[row*4 + wn] = s; }
        }
    }
    __syncthreads();
    if (tid < 64) {
        float m = red_m[tid*4], s = red_s[tid*4];
        #pragma unroll
        for (int j = 1; j < 4; j++) {
            float m2 = red_m[tid*4 + j], s2 = red_s[tid*4 + j];
            float nm = fmaxf(m, m2);
            s = s*__expf(m - nm) + s2*__expf(m2 - nm);
            m = nm;
        }
        g_pm[(size_t)(tok0 + tid)*NTI + blockIdx.x] = m;
        g_ps[(size_t)(tok0 + tid)*NTI + blockIdx.x] = s;
    }
}

// ---------------- per-token NLL from partials ------------------------------
__global__ void loss_token_k(const float* __restrict__ logits,
                             const int* __restrict__ targets) {
    int tok = blockIdx.x;
    int lane = threadIdx.x;                  // 32
    float m = -1e30f, s = 0.f;
    for (int i = lane; i < NTI; i += 32) {
        float m2 = g_pm[(size_t)tok*NTI + i];
        float s2 = g_ps[(size_t)tok*NTI + i];
        float nm = fmaxf(m, m2);
        s = s*__expf(m - nm) + s2*__expf(m2 - nm);
        m = nm;
    }
    #pragma unroll
    for (int o = 16; o; o >>= 1) {
        float m2 = __shfl_xor_sync(0xffffffffu, m, o);
        float s2 = __shfl_xor_sync(0xffffffffu, s, o);
        float nm = fmaxf(m, m2);
        s = s*__expf(m - nm) + s2*__expf(m2 - nm);
        m = nm;
    }
    if (lane == 0) {
        float lse = m + logf(s);
        g_nll[tok] = lse - logits[(size_t)tok*Vv + targets[tok]];
    }
}

__global__ void loss_reduce_k(float* __restrict__ out) {
    int tid = threadIdx.x;                    // 256
    float s = 0.f;
    for (int i = tid; i < NT; i += 256) s += g_nll[i];
    #pragma unroll
    for (int o = 16; o; o >>= 1) s += __shfl_xor_sync(0xffffffffu, s, o);
    __shared__ float r[8];
    if ((tid & 31) == 0) r[tid >> 5] = s;
    __syncthreads();
    if (tid == 0) {
        float t = 0.f;
        #pragma unroll
        for (int i = 0; i < 8; i++) t += r[i];
        out[(size_t)NT * Vv] = t * (1.f / NT);
    }
}

// ---------------- launcher -------------------------------------------------
extern "C" void kernel_launch(void* const* d_in, const int* in_sizes, int n_in,
                              void* d_out, int out_size) {
    const int*   idx     = (const int*)d_in[0];
    const int*   targets = (const int*)d_in[1];
    const float* tok_emb = (const float*)d_in[2];
    const float* pos_emb = (const float*)d_in[3];
    const float* wq      = (const float*)d_in[4];
    const float* wk      = (const float*)d_in[5];
    const float* wv      = (const float*)d_in[6];
    const float* wproj   = (const float*)d_in[7];
    const float* bproj   = (const float*)d_in[8];
    const float* w1      = (const float*)d_in[9];
    const float* b1      = (const float*)d_in[10];
    const float* w2      = (const float*)d_in[11];
    const float* b2      = (const float*)d_in[12];
    const float* ln1_g   = (const float*)d_in[13];
    const float* ln1_b   = (const float*)d_in[14];
    const float* ln2_g   = (const float*)d_in[15];
    const float* ln2_b   = (const float*)d_in[16];
    const float* lnf_g   = (const float*)d_in[17];
    const float* lnf_b   = (const float*)d_in[18];
    const float* lm_w    = (const float*)d_in[19];
    const float* lm_b    = (const float*)d_in[20];
    float* out = (float*)d_out;

    float *px, *ph, *po, *pmlp;
    cudaGetSymbolAddress((void**)&px, g_x);
    cudaGetSymbolAddress((void**)&ph, g_h);
    cudaGetSymbolAddress((void**)&po, g_o);
    cudaGetSymbolAddress((void**)&pmlp, g_mlp);

    static int smem_set = 0;
    if (!smem_set) {
        cudaFuncSetAttribute(logits_mma_k,
                             cudaFuncAttributeMaxDynamicSharedMemorySize, SMEM_LM);
        smem_set = 1;
    }

    embed_k<<<NT, Dv>>>(idx, tok_emb, pos_emb);
    wsplit_k<<<dim3(Wpad/128, Dv), 128>>>(lm_w);

    for (int l = 0; l < Lv; l++) {
        const float* wq_l = wq + (size_t)l*Hv*Dv*HDv;
        const float* wk_l = wk + (size_t)l*Hv*Dv*HDv;
        const float* wv_l = wv + (size_t)l*Hv*Dv*HDv;
        ln_k<<<NT, Dv>>>(px, ph, ln1_g + l*Dv, ln1_b + l*Dv);
        qkv_k2<<<NT/32, 256>>>(ph, wq_l, wk_l, wv_l);
        attn_k<<<Bv*Hv, Tv>>>();
        gemm_body_k<0,1><<<dim3(1, NT/32), 256>>>(
            po, wproj + (size_t)l*Dv*Dv, bproj + l*Dv, px, Dv, Dv);
        ln_k<<<NT, Dv>>>(px, ph, ln2_g + l*Dv, ln2_b + l*Dv);
        gemm_body_k<1,0><<<dim3(4, NT/32), 256>>>(
            ph, w1 + (size_t)l*Dv*4*Dv, b1 + l*4*Dv, pmlp, 4*Dv, Dv);
        gemm_body_k<0,1><<<dim3(1, NT/32), 256>>>(
            pmlp, w2 + (size_t)l*4*Dv*Dv, b2 + l*Dv, px, Dv, 4*Dv);
    }

    ln_k<<<NT, Dv>>>(px, ph, lnf_g, lnf_b);
    hsplit_k<<<NT*Dv/256, 256>>>(ph);

    logits_mma_k<<<dim3(NTI, NT/64), 256, SMEM_LM>>>(out, lm_b);

    loss_token_k<<<NT, 32>>>(out, targets);
    loss_reduce_k<<<1, 256>>>(out);
}